// round 5
// baseline (speedup 1.0000x reference)
#include <cuda_runtime.h>
#include <cstddef>

// Problem constants
#define B_   4
#define C_   3072
#define T_   4096
#define KJ   24
#define CPJ_ 128
#define TD_  128
#define TT   4            // tokens (t values) per CTA
#define NROW (TT*KJ)      // 96 batched rows per CTA
#define STR  132          // padded row stride (floats) for activation buffers
#define NTH  512

#define EPSF   1e-5f
#define SCALEF 0.08838834764831845f   // 128^-0.5

// smem layout (floats): sW[16384] | sTok[96*132] | sU[96*132] | sV[96*132] | sS[96*24] | sBias[128] | sGn[128]
#define SMEM_FLOATS (16384 + 3*NROW*STR + NROW*KJ + 256)

// ---------- packed f32x2 helpers (Blackwell FFMA2: 2 fp32 MACs per instr) ----------
__device__ __forceinline__ unsigned long long pk2(float lo, float hi) {
    unsigned long long r;
    asm("mov.b64 %0, {%1, %2};" : "=l"(r) : "f"(lo), "f"(hi));
    return r;
}
__device__ __forceinline__ void fma2(unsigned long long &d, unsigned long long a, unsigned long long b) {
    asm("fma.rn.f32x2 %0, %1, %2, %0;" : "+l"(d) : "l"(a), "l"(b));
}
__device__ __forceinline__ float2 unpk2(unsigned long long v) {
    float2 r;
    asm("mov.b64 {%0, %1}, %2;" : "=f"(r.x), "=f"(r.y) : "l"(v));
    return r;
}

// ---------- stage a 128x128 fp32 weight block into smem (coalesced float4) ----------
__device__ __forceinline__ void load_w128(const float* __restrict__ g, int ld, int off,
                                          float* sW, int tid) {
#pragma unroll
    for (int it = 0; it < 8; ++it) {
        int idx = tid + it * NTH;           // 4096 float4 total
        int c  = idx >> 5;
        int d4 = (idx & 31) << 2;
        *reinterpret_cast<float4*>(sW + c * 128 + d4) =
            *reinterpret_cast<const float4*>(g + (size_t)c * ld + off + d4);
    }
}

// ---------- batched GEMM: OUT[96][128] = IN[96][128] @ W[128][128] + bias ----------
// warp r0 owns rows r0*6..r0*6+5; lane d0 owns columns 4*d0..4*d0+3.
// IN loads are warp-uniform broadcasts (conflict-free); W loads are LDS.128.
__device__ __forceinline__ void gemm_smem(const float* sIn, const float* sW, const float* sB,
                                          float* sOut, int r0, int d0) {
    unsigned long long acc[6][2];
    {
        ulonglong2 bp = *reinterpret_cast<const ulonglong2*>(sB + 4 * d0);
#pragma unroll
        for (int i = 0; i < 6; ++i) { acc[i][0] = bp.x; acc[i][1] = bp.y; }
    }
    const float* in = sIn + r0 * 6 * STR;
    const float* w  = sW + 4 * d0;
#pragma unroll 2
    for (int c = 0; c < 128; c += 2) {
        ulonglong2 w0 = *reinterpret_cast<const ulonglong2*>(w + c * 128);
        ulonglong2 w1 = *reinterpret_cast<const ulonglong2*>(w + (c + 1) * 128);
#pragma unroll
        for (int i = 0; i < 6; ++i) {
            float2 a = *reinterpret_cast<const float2*>(in + i * STR + c);
            unsigned long long a0 = pk2(a.x, a.x);
            unsigned long long a1 = pk2(a.y, a.y);
            fma2(acc[i][0], a0, w0.x); fma2(acc[i][1], a0, w0.y);
            fma2(acc[i][0], a1, w1.x); fma2(acc[i][1], a1, w1.y);
        }
    }
#pragma unroll
    for (int i = 0; i < 6; ++i) {
        float2 l = unpk2(acc[i][0]);
        float2 h = unpk2(acc[i][1]);
        *reinterpret_cast<float4*>(sOut + (r0 * 6 + i) * STR + 4 * d0) =
            make_float4(l.x, l.y, h.x, h.y);
    }
}

__global__ void __launch_bounds__(NTH, 1)
wanjoint_kernel(const float* __restrict__ x,
                const float* __restrict__ W_tok,  const float* __restrict__ b_tok,
                const float* __restrict__ g_norm,
                const float* __restrict__ W_qkv,  const float* __restrict__ b_qkv,
                const float* __restrict__ W_proj, const float* __restrict__ b_proj,
                const float* __restrict__ W_from, const float* __restrict__ b_from,
                float* __restrict__ out)
{
    extern __shared__ float smem[];
    float* sW    = smem;                    // 16384
    float* sTok  = sW   + 16384;            // 96*132
    float* sU    = sTok + NROW * STR;
    float* sV    = sU   + NROW * STR;
    float* sS    = sV   + NROW * STR;       // 96*24
    float* sBias = sS   + NROW * KJ;        // 128
    float* sGn   = sBias + 128;             // 128

    const int tid = threadIdx.x;
    const int d0  = tid & 31;
    const int r0  = tid >> 5;
    const int b   = blockIdx.x >> 10;          // T_/TT = 1024 groups per batch
    const int t0  = (blockIdx.x & 1023) * TT;

    // ---- phase 0: stage W_tok / b_tok / g_norm ----
    load_w128(W_tok, 128, 0, sW, tid);
    if (tid < 128) { sBias[tid] = b_tok[tid]; sGn[tid] = g_norm[tid]; }
    __syncthreads();

    // ---- stage 1: tok = x @ W_tok + b_tok  (IN read straight from global) ----
    {
        const float* xr[6];
#pragma unroll
        for (int i = 0; i < 6; ++i) {
            int r  = r0 * 6 + i;
            int tl = r / KJ;          // local token 0..3 (rows of a warp share a token)
            int j  = r % KJ;          // joint
            xr[i] = x + ((size_t)b * C_ + (size_t)j * CPJ_) * T_ + (t0 + tl);
        }
        unsigned long long acc[6][2];
        {
            ulonglong2 bp = *reinterpret_cast<const ulonglong2*>(sBias + 4 * d0);
#pragma unroll
            for (int i = 0; i < 6; ++i) { acc[i][0] = bp.x; acc[i][1] = bp.y; }
        }
        const float* w = sW + 4 * d0;
#pragma unroll 2
        for (int c = 0; c < 128; c += 2) {
            ulonglong2 w0 = *reinterpret_cast<const ulonglong2*>(w + c * 128);
            ulonglong2 w1 = *reinterpret_cast<const ulonglong2*>(w + (c + 1) * 128);
#pragma unroll
            for (int i = 0; i < 6; ++i) {
                float ax = __ldg(xr[i] + c * T_);
                float ay = __ldg(xr[i] + (c + 1) * T_);
                unsigned long long a0 = pk2(ax, ax);
                unsigned long long a1 = pk2(ay, ay);
                fma2(acc[i][0], a0, w0.x); fma2(acc[i][1], a0, w0.y);
                fma2(acc[i][0], a1, w1.x); fma2(acc[i][1], a1, w1.y);
            }
        }
#pragma unroll
        for (int i = 0; i < 6; ++i) {
            float2 l = unpk2(acc[i][0]);
            float2 h = unpk2(acc[i][1]);
            *reinterpret_cast<float4*>(sTok + (r0 * 6 + i) * STR + 4 * d0) =
                make_float4(l.x, l.y, h.x, h.y);
        }
    }

    // ---- RMSNorm (warp-local rows, no block sync needed before this) ----
#pragma unroll
    for (int i = 0; i < 6; ++i) {
        float* row = sTok + (r0 * 6 + i) * STR;
        float v0 = row[d0], v1 = row[d0 + 32], v2 = row[d0 + 64], v3 = row[d0 + 96];
        float s = v0 * v0 + v1 * v1 + v2 * v2 + v3 * v3;
#pragma unroll
        for (int o = 16; o > 0; o >>= 1) s += __shfl_xor_sync(0xffffffffu, s, o);
        float sc = rsqrtf(s * (1.0f / 128.0f) + EPSF);
        row[d0]      = v0 * sc * sGn[d0];
        row[d0 + 32] = v1 * sc * sGn[d0 + 32];
        row[d0 + 64] = v2 * sc * sGn[d0 + 64];
        row[d0 + 96] = v3 * sc * sGn[d0 + 96];
    }
    __syncthreads();

    // ---- Q = tok @ Wq + bq -> sU ----
    load_w128(W_qkv, 3 * TD_, 0, sW, tid);
    if (tid < 128) sBias[tid] = b_qkv[tid];
    __syncthreads();
    gemm_smem(sTok, sW, sBias, sU, r0, d0);
    __syncthreads();

    // ---- K = tok @ Wk + bk -> sV ----
    load_w128(W_qkv, 3 * TD_, 128, sW, tid);
    if (tid < 128) sBias[tid] = b_qkv[128 + tid];
    __syncthreads();
    gemm_smem(sTok, sW, sBias, sV, r0, d0);
    __syncthreads();

    // ---- prefetch Wv into sW (no one reads sW until V gemm, after 2 syncs) ----
    load_w128(W_qkv, 3 * TD_, 256, sW, tid);
    if (tid < 128) sBias[tid] = b_qkv[256 + tid];

    // ---- scores S[i][j] = scale * q_i . k_j  (warp handles its 6 rows; lanes 0..23 = j) ----
    if (d0 < KJ) {
        const int tt4 = r0 >> 2;                          // local token of this warp's rows
        const float* krow = sV + (tt4 * KJ + d0) * STR;
#pragma unroll
        for (int i = 0; i < 6; ++i) {
            const float* qrow = sU + (r0 * 6 + i) * STR;
            float s = 0.0f;
#pragma unroll 8
            for (int d = 0; d < 128; d += 2) {
                float2 qv = *reinterpret_cast<const float2*>(qrow + d);
                float2 kv = *reinterpret_cast<const float2*>(krow + d);
                s += qv.x * kv.x + qv.y * kv.y;
            }
            sS[(r0 * 6 + i) * KJ + d0] = s * SCALEF;
        }
    }
    __syncthreads();

    // ---- softmax over j (24) per row ----
    if (tid < NROW) {
        float* row = sS + tid * KJ;
        float m = row[0];
#pragma unroll
        for (int j = 1; j < KJ; ++j) m = fmaxf(m, row[j]);
        float sum = 0.0f;
#pragma unroll
        for (int j = 0; j < KJ; ++j) { float e = __expf(row[j] - m); row[j] = e; sum += e; }
        float inv = 1.0f / sum;
#pragma unroll
        for (int j = 0; j < KJ; ++j) row[j] *= inv;
    }
    __syncthreads();

    // ---- V = tok @ Wv + bv -> sU (q is dead) ----
    gemm_smem(sTok, sW, sBias, sU, r0, d0);
    __syncthreads();

    // ---- attn out = P @ V -> sV (k is dead) ----
    {
        unsigned long long acc[6][2];
#pragma unroll
        for (int i = 0; i < 6; ++i) { acc[i][0] = 0ull; acc[i][1] = 0ull; }
        const int tt4 = r0 >> 2;
        const float* vb = sU + tt4 * KJ * STR + 4 * d0;
        const float* pb = sS + r0 * 6 * KJ;
#pragma unroll 4
        for (int j = 0; j < KJ; ++j) {
            ulonglong2 v2 = *reinterpret_cast<const ulonglong2*>(vb + j * STR);
#pragma unroll
            for (int i = 0; i < 6; ++i) {
                float p = pb[i * KJ + j];
                unsigned long long pp = pk2(p, p);
                fma2(acc[i][0], pp, v2.x);
                fma2(acc[i][1], pp, v2.y);
            }
        }
#pragma unroll
        for (int i = 0; i < 6; ++i) {
            float2 l = unpk2(acc[i][0]);
            float2 h = unpk2(acc[i][1]);
            *reinterpret_cast<float4*>(sV + (r0 * 6 + i) * STR + 4 * d0) =
                make_float4(l.x, l.y, h.x, h.y);
        }
    }
    __syncthreads();

    // ---- proj: sV @ W_proj + b_proj -> sTok (tok is dead) ----
    load_w128(W_proj, 128, 0, sW, tid);
    if (tid < 128) sBias[tid] = b_proj[tid];
    __syncthreads();
    gemm_smem(sV, sW, sBias, sTok, r0, d0);
    __syncthreads();

    // ---- from: sTok @ W_from + b_from -> sU (v is dead) ----
    load_w128(W_from, 128, 0, sW, tid);
    if (tid < 128) sBias[tid] = b_from[tid];
    __syncthreads();
    gemm_smem(sTok, sW, sBias, sU, r0, d0);
    __syncthreads();

    // ---- residual add + write out in [B, C, T] layout ----
    {
        const size_t base = (size_t)b * C_ * T_;
#pragma unroll
        for (int it = 0; it < (C_ * TT) / NTH; ++it) {
            int idx = tid + it * NTH;        // 0 .. 12287
            int tl  = idx & 3;
            int ch  = idx >> 2;              // 0 .. 3071
            int j   = ch >> 7;
            int c   = ch & 127;
            size_t g = base + (size_t)ch * T_ + t0 + tl;
            out[g] = x[g] + sU[(tl * KJ + j) * STR + c];
        }
    }
}

extern "C" void kernel_launch(void* const* d_in, const int* in_sizes, int n_in,
                              void* d_out, int out_size) {
    (void)in_sizes; (void)n_in; (void)out_size;
    const float* x      = (const float*)d_in[0];
    const float* W_tok  = (const float*)d_in[1];
    const float* b_tok  = (const float*)d_in[2];
    const float* g_norm = (const float*)d_in[3];
    const float* W_qkv  = (const float*)d_in[4];
    const float* b_qkv  = (const float*)d_in[5];
    const float* W_proj = (const float*)d_in[6];
    const float* b_proj = (const float*)d_in[7];
    const float* W_from = (const float*)d_in[8];
    const float* b_from = (const float*)d_in[9];
    float* out = (float*)d_out;

    const int smem_bytes = SMEM_FLOATS * (int)sizeof(float);   // 227840 B
    cudaFuncSetAttribute(wanjoint_kernel,
                         cudaFuncAttributeMaxDynamicSharedMemorySize, smem_bytes);

    dim3 grid(B_ * (T_ / TT));   // 4096 CTAs
    dim3 block(NTH);             // 512 threads
    wanjoint_kernel<<<grid, block, smem_bytes>>>(
        x, W_tok, b_tok, g_norm, W_qkv, b_qkv, W_proj, b_proj, W_from, b_from, out);
}

// round 6
// speedup vs baseline: 1.0027x; 1.0027x over previous
#include <cuda_runtime.h>
#include <cstddef>

// Problem constants
#define B_   4
#define C_   3072
#define T_   4096
#define KJ   24
#define CPJ_ 128
#define TD_  128
#define TT   4            // tokens (t values) per CTA
#define NROW (TT*KJ)      // 96 batched rows per CTA
#define STR  132          // padded row stride (floats) for activation buffers
#define NTH  512

#define EPSF   1e-5f
#define SCALEF 0.08838834764831845f   // 128^-0.5

// smem layout (floats): sW[16384] | sTok[96*132] | sU[96*132] | sV[96*132] | sS[96*24] | sBias[128] | sGn[128]
#define SMEM_FLOATS (16384 + 3*NROW*STR + NROW*KJ + 256)

// ---------- packed f32x2 helpers (Blackwell FFMA2: 2 fp32 MACs per instr) ----------
__device__ __forceinline__ unsigned long long pk2(float lo, float hi) {
    unsigned long long r;
    asm("mov.b64 %0, {%1, %2};" : "=l"(r) : "f"(lo), "f"(hi));
    return r;
}
__device__ __forceinline__ void fma2(unsigned long long &d, unsigned long long a, unsigned long long b) {
    asm("fma.rn.f32x2 %0, %1, %2, %0;" : "+l"(d) : "l"(a), "l"(b));
}
__device__ __forceinline__ float2 unpk2(unsigned long long v) {
    float2 r;
    asm("mov.b64 {%0, %1}, %2;" : "=f"(r.x), "=f"(r.y) : "l"(v));
    return r;
}

// ---------- stage a 128x128 fp32 weight block into smem (coalesced float4) ----------
__device__ __forceinline__ void load_w128(const float* __restrict__ g, int ld, int off,
                                          float* sW, int tid) {
#pragma unroll
    for (int it = 0; it < 8; ++it) {
        int idx = tid + it * NTH;           // 4096 float4 total
        int c  = idx >> 5;
        int d4 = (idx & 31) << 2;
        *reinterpret_cast<float4*>(sW + c * 128 + d4) =
            *reinterpret_cast<const float4*>(g + (size_t)c * ld + off + d4);
    }
}

// ---------- batched GEMM: OUT[96][128] = IN[96][128] @ W[128][128] + bias ----------
// warp r0 owns rows r0*6..r0*6+5; lane d0 owns columns 4*d0..4*d0+3.
// IN loads are warp-uniform broadcasts (conflict-free); W loads are LDS.128.
__device__ __forceinline__ void gemm_smem(const float* sIn, const float* sW, const float* sB,
                                          float* sOut, int r0, int d0) {
    unsigned long long acc[6][2];
    {
        ulonglong2 bp = *reinterpret_cast<const ulonglong2*>(sB + 4 * d0);
#pragma unroll
        for (int i = 0; i < 6; ++i) { acc[i][0] = bp.x; acc[i][1] = bp.y; }
    }
    const float* in = sIn + r0 * 6 * STR;
    const float* w  = sW + 4 * d0;
#pragma unroll 2
    for (int c = 0; c < 128; c += 2) {
        ulonglong2 w0 = *reinterpret_cast<const ulonglong2*>(w + c * 128);
        ulonglong2 w1 = *reinterpret_cast<const ulonglong2*>(w + (c + 1) * 128);
#pragma unroll
        for (int i = 0; i < 6; ++i) {
            float2 a = *reinterpret_cast<const float2*>(in + i * STR + c);
            unsigned long long a0 = pk2(a.x, a.x);
            unsigned long long a1 = pk2(a.y, a.y);
            fma2(acc[i][0], a0, w0.x); fma2(acc[i][1], a0, w0.y);
            fma2(acc[i][0], a1, w1.x); fma2(acc[i][1], a1, w1.y);
        }
    }
#pragma unroll
    for (int i = 0; i < 6; ++i) {
        float2 l = unpk2(acc[i][0]);
        float2 h = unpk2(acc[i][1]);
        *reinterpret_cast<float4*>(sOut + (r0 * 6 + i) * STR + 4 * d0) =
            make_float4(l.x, l.y, h.x, h.y);
    }
}

__global__ void __launch_bounds__(NTH, 1)
wanjoint_kernel(const float* __restrict__ x,
                const float* __restrict__ W_tok,  const float* __restrict__ b_tok,
                const float* __restrict__ g_norm,
                const float* __restrict__ W_qkv,  const float* __restrict__ b_qkv,
                const float* __restrict__ W_proj, const float* __restrict__ b_proj,
                const float* __restrict__ W_from, const float* __restrict__ b_from,
                float* __restrict__ out)
{
    extern __shared__ float smem[];
    float* sW    = smem;                    // 16384
    float* sTok  = sW   + 16384;            // 96*132
    float* sU    = sTok + NROW * STR;
    float* sV    = sU   + NROW * STR;
    float* sS    = sV   + NROW * STR;       // 96*24
    float* sBias = sS   + NROW * KJ;        // 128
    float* sGn   = sBias + 128;             // 128

    const int tid = threadIdx.x;
    const int d0  = tid & 31;
    const int r0  = tid >> 5;
    const int b   = blockIdx.x >> 10;          // T_/TT = 1024 groups per batch
    const int t0  = (blockIdx.x & 1023) * TT;

    // ---- phase 0: stage W_tok / b_tok / g_norm ----
    load_w128(W_tok, 128, 0, sW, tid);
    if (tid < 128) { sBias[tid] = b_tok[tid]; sGn[tid] = g_norm[tid]; }
    __syncthreads();

    // ---- stage 1: tok = x @ W_tok + b_tok  (IN read straight from global) ----
    {
        const float* xr[6];
#pragma unroll
        for (int i = 0; i < 6; ++i) {
            int r  = r0 * 6 + i;
            int tl = r / KJ;          // local token 0..3 (rows of a warp share a token)
            int j  = r % KJ;          // joint
            xr[i] = x + ((size_t)b * C_ + (size_t)j * CPJ_) * T_ + (t0 + tl);
        }
        unsigned long long acc[6][2];
        {
            ulonglong2 bp = *reinterpret_cast<const ulonglong2*>(sBias + 4 * d0);
#pragma unroll
            for (int i = 0; i < 6; ++i) { acc[i][0] = bp.x; acc[i][1] = bp.y; }
        }
        const float* w = sW + 4 * d0;
#pragma unroll 2
        for (int c = 0; c < 128; c += 2) {
            ulonglong2 w0 = *reinterpret_cast<const ulonglong2*>(w + c * 128);
            ulonglong2 w1 = *reinterpret_cast<const ulonglong2*>(w + (c + 1) * 128);
#pragma unroll
            for (int i = 0; i < 6; ++i) {
                float ax = __ldg(xr[i] + c * T_);
                float ay = __ldg(xr[i] + (c + 1) * T_);
                unsigned long long a0 = pk2(ax, ax);
                unsigned long long a1 = pk2(ay, ay);
                fma2(acc[i][0], a0, w0.x); fma2(acc[i][1], a0, w0.y);
                fma2(acc[i][0], a1, w1.x); fma2(acc[i][1], a1, w1.y);
            }
        }
#pragma unroll
        for (int i = 0; i < 6; ++i) {
            float2 l = unpk2(acc[i][0]);
            float2 h = unpk2(acc[i][1]);
            *reinterpret_cast<float4*>(sTok + (r0 * 6 + i) * STR + 4 * d0) =
                make_float4(l.x, l.y, h.x, h.y);
        }
    }

    // ---- RMSNorm (warp-local rows, no block sync needed before this) ----
#pragma unroll
    for (int i = 0; i < 6; ++i) {
        float* row = sTok + (r0 * 6 + i) * STR;
        float v0 = row[d0], v1 = row[d0 + 32], v2 = row[d0 + 64], v3 = row[d0 + 96];
        float s = v0 * v0 + v1 * v1 + v2 * v2 + v3 * v3;
#pragma unroll
        for (int o = 16; o > 0; o >>= 1) s += __shfl_xor_sync(0xffffffffu, s, o);
        float sc = rsqrtf(s * (1.0f / 128.0f) + EPSF);
        row[d0]      = v0 * sc * sGn[d0];
        row[d0 + 32] = v1 * sc * sGn[d0 + 32];
        row[d0 + 64] = v2 * sc * sGn[d0 + 64];
        row[d0 + 96] = v3 * sc * sGn[d0 + 96];
    }
    __syncthreads();

    // ---- Q = tok @ Wq + bq -> sU ----
    load_w128(W_qkv, 3 * TD_, 0, sW, tid);
    if (tid < 128) sBias[tid] = b_qkv[tid];
    __syncthreads();
    gemm_smem(sTok, sW, sBias, sU, r0, d0);
    __syncthreads();

    // ---- K = tok @ Wk + bk -> sV ----
    load_w128(W_qkv, 3 * TD_, 128, sW, tid);
    if (tid < 128) sBias[tid] = b_qkv[128 + tid];
    __syncthreads();
    gemm_smem(sTok, sW, sBias, sV, r0, d0);
    __syncthreads();

    // ---- prefetch Wv into sW (no one reads sW until V gemm, after 2 syncs) ----
    load_w128(W_qkv, 3 * TD_, 256, sW, tid);
    if (tid < 128) sBias[tid] = b_qkv[256 + tid];

    // ---- scores S[i][j] = scale * q_i . k_j  (warp handles its 6 rows; lanes 0..23 = j) ----
    if (d0 < KJ) {
        const int tt4 = r0 >> 2;                          // local token of this warp's rows
        const float* krow = sV + (tt4 * KJ + d0) * STR;
#pragma unroll
        for (int i = 0; i < 6; ++i) {
            const float* qrow = sU + (r0 * 6 + i) * STR;
            float s = 0.0f;
#pragma unroll 8
            for (int d = 0; d < 128; d += 2) {
                float2 qv = *reinterpret_cast<const float2*>(qrow + d);
                float2 kv = *reinterpret_cast<const float2*>(krow + d);
                s += qv.x * kv.x + qv.y * kv.y;
            }
            sS[(r0 * 6 + i) * KJ + d0] = s * SCALEF;
        }
    }
    __syncthreads();

    // ---- softmax over j (24) per row ----
    if (tid < NROW) {
        float* row = sS + tid * KJ;
        float m = row[0];
#pragma unroll
        for (int j = 1; j < KJ; ++j) m = fmaxf(m, row[j]);
        float sum = 0.0f;
#pragma unroll
        for (int j = 0; j < KJ; ++j) { float e = __expf(row[j] - m); row[j] = e; sum += e; }
        float inv = 1.0f / sum;
#pragma unroll
        for (int j = 0; j < KJ; ++j) row[j] *= inv;
    }
    __syncthreads();

    // ---- V = tok @ Wv + bv -> sU (q is dead) ----
    gemm_smem(sTok, sW, sBias, sU, r0, d0);
    __syncthreads();

    // ---- attn out = P @ V -> sV (k is dead) ----
    {
        unsigned long long acc[6][2];
#pragma unroll
        for (int i = 0; i < 6; ++i) { acc[i][0] = 0ull; acc[i][1] = 0ull; }
        const int tt4 = r0 >> 2;
        const float* vb = sU + tt4 * KJ * STR + 4 * d0;
        const float* pb = sS + r0 * 6 * KJ;
#pragma unroll 4
        for (int j = 0; j < KJ; ++j) {
            ulonglong2 v2 = *reinterpret_cast<const ulonglong2*>(vb + j * STR);
#pragma unroll
            for (int i = 0; i < 6; ++i) {
                float p = pb[i * KJ + j];
                unsigned long long pp = pk2(p, p);
                fma2(acc[i][0], pp, v2.x);
                fma2(acc[i][1], pp, v2.y);
            }
        }
#pragma unroll
        for (int i = 0; i < 6; ++i) {
            float2 l = unpk2(acc[i][0]);
            float2 h = unpk2(acc[i][1]);
            *reinterpret_cast<float4*>(sV + (r0 * 6 + i) * STR + 4 * d0) =
                make_float4(l.x, l.y, h.x, h.y);
        }
    }
    __syncthreads();

    // ---- proj: sV @ W_proj + b_proj -> sTok (tok is dead) ----
    load_w128(W_proj, 128, 0, sW, tid);
    if (tid < 128) sBias[tid] = b_proj[tid];
    __syncthreads();
    gemm_smem(sV, sW, sBias, sTok, r0, d0);
    __syncthreads();

    // ---- from: sTok @ W_from + b_from -> sU (v is dead) ----
    load_w128(W_from, 128, 0, sW, tid);
    if (tid < 128) sBias[tid] = b_from[tid];
    __syncthreads();
    gemm_smem(sTok, sW, sBias, sU, r0, d0);
    __syncthreads();

    // ---- residual add + write out in [B, C, T] layout ----
    {
        const size_t base = (size_t)b * C_ * T_;
#pragma unroll
        for (int it = 0; it < (C_ * TT) / NTH; ++it) {
            int idx = tid + it * NTH;        // 0 .. 12287
            int tl  = idx & 3;
            int ch  = idx >> 2;              // 0 .. 3071
            int j   = ch >> 7;
            int c   = ch & 127;
            size_t g = base + (size_t)ch * T_ + t0 + tl;
            out[g] = x[g] + sU[(tl * KJ + j) * STR + c];
        }
    }
}

extern "C" void kernel_launch(void* const* d_in, const int* in_sizes, int n_in,
                              void* d_out, int out_size) {
    (void)in_sizes; (void)n_in; (void)out_size;
    const float* x      = (const float*)d_in[0];
    const float* W_tok  = (const float*)d_in[1];
    const float* b_tok  = (const float*)d_in[2];
    const float* g_norm = (const float*)d_in[3];
    const float* W_qkv  = (const float*)d_in[4];
    const float* b_qkv  = (const float*)d_in[5];
    const float* W_proj = (const float*)d_in[6];
    const float* b_proj = (const float*)d_in[7];
    const float* W_from = (const float*)d_in[8];
    const float* b_from = (const float*)d_in[9];
    float* out = (float*)d_out;

    const int smem_bytes = SMEM_FLOATS * (int)sizeof(float);   // 227840 B
    cudaFuncSetAttribute(wanjoint_kernel,
                         cudaFuncAttributeMaxDynamicSharedMemorySize, smem_bytes);

    dim3 grid(B_ * (T_ / TT));   // 4096 CTAs
    dim3 block(NTH);             // 512 threads
    wanjoint_kernel<<<grid, block, smem_bytes>>>(
        x, W_tok, b_tok, g_norm, W_qkv, b_qkv, W_proj, b_proj, W_from, b_from, out);
}

// round 11
// speedup vs baseline: 2.2490x; 2.2430x over previous
#include <cuda_runtime.h>
#include <cuda_bf16.h>
#include <cstdint>
#include <cstddef>

// ---------------- problem constants ----------------
#define B_    4
#define C_    3072
#define T_    4096
#define KJ    24
#define NROW  96
#define NTHR  256
#define SCALEF 0.08838834764831845f
#define EPSF   1e-5f

#define ASTB  272      // bf16 tile row stride in bytes (136 elems; odd x16B -> ldmatrix conflict-free)

// ---------------- smem offsets (bytes) ----------------
#define SO_AHI  0
#define SO_ALO  26112          // 96*272
#define SO_BHI  52224
#define SO_BLO  87040          // +128*272
#define SO_BUF  121856         // 96*132 fp32 = 50688
#define SO_P    172544         // 96*24 fp32 = 9216
#define SO_BIAS 181760         // 896 fp32 = 3584
#define SO_SQ   185344         // 96 fp32
#define SMEM_TOTAL 185728

// preconverted weights: [tile][hi/lo][n*136 + k] bf16 (B[n][k] = W[k][n])
// tiles: 0=W_tok^T 1=Wq^T 2=Wk^T 3=Wv^T 4=W_proj^T 5=W_from^T
__device__ __align__(16) __nv_bfloat16 g_wt[6][2][128 * 136];

// ---------------- helpers ----------------
__device__ __forceinline__ uint32_t smem_u32(const void* p) {
    uint32_t a;
    asm("{ .reg .u64 t; cvta.to.shared.u64 t, %1; cvt.u32.u64 %0, t; }" : "=r"(a) : "l"(p));
    return a;
}
__device__ __forceinline__ void ldsm4(uint32_t a, uint32_t r[4]) {
    asm volatile("ldmatrix.sync.aligned.m8n8.x4.shared.b16 {%0,%1,%2,%3}, [%4];"
        : "=r"(r[0]), "=r"(r[1]), "=r"(r[2]), "=r"(r[3]) : "r"(a));
}
__device__ __forceinline__ void mma16816(float d[4], const uint32_t a[4], uint32_t b0, uint32_t b1) {
    asm volatile("mma.sync.aligned.m16n8k16.row.col.f32.bf16.bf16.f32 "
        "{%0,%1,%2,%3}, {%4,%5,%6,%7}, {%8,%9}, {%0,%1,%2,%3};"
        : "+f"(d[0]), "+f"(d[1]), "+f"(d[2]), "+f"(d[3])
        : "r"(a[0]), "r"(a[1]), "r"(a[2]), "r"(a[3]), "r"(b0), "r"(b1));
}
__device__ __forceinline__ unsigned long long pk2(float lo, float hi) {
    unsigned long long r;
    asm("mov.b64 %0, {%1, %2};" : "=l"(r) : "f"(lo), "f"(hi));
    return r;
}
__device__ __forceinline__ void fma2(unsigned long long& d, unsigned long long a, unsigned long long b) {
    asm("fma.rn.f32x2 %0, %1, %2, %0;" : "+l"(d) : "l"(a), "l"(b));
}
__device__ __forceinline__ float2 unpk2(unsigned long long v) {
    float2 r;
    asm("mov.b64 {%0, %1}, %2;" : "=f"(r.x), "=f"(r.y) : "l"(v));
    return r;
}

// hi/lo bf16 split + paired store into linear stride-136 tile (col even)
__device__ __forceinline__ void split_store(char* hi, char* lo, int row, int col, float a, float b) {
    __nv_bfloat162 h = __floats2bfloat162_rn(a, b);
    float ra = a - __bfloat162float(h.x);
    float rb = b - __bfloat162float(h.y);
    __nv_bfloat162 l = __floats2bfloat162_rn(ra, rb);
    int o = row * ASTB + col * 2;
    *reinterpret_cast<__nv_bfloat162*>(hi + o) = h;
    *reinterpret_cast<__nv_bfloat162*>(lo + o) = l;
}

// ---------------- prep: transpose + hi/lo split ----------------
__global__ void wan_prep(const float* __restrict__ Wtok, const float* __restrict__ Wqkv,
                         const float* __restrict__ Wproj, const float* __restrict__ Wfrom) {
    int idx = blockIdx.x * blockDim.x + threadIdx.x;     // 6*16384
    if (idx >= 6 * 16384) return;
    int tile = idx >> 14;
    int r = idx & 16383;
    int n = r >> 7, k = r & 127;
    float w;
    switch (tile) {
        case 0: w = Wtok[k * 128 + n]; break;
        case 1: w = Wqkv[k * 384 + n]; break;
        case 2: w = Wqkv[k * 384 + 128 + n]; break;
        case 3: w = Wqkv[k * 384 + 256 + n]; break;
        case 4: w = Wproj[k * 128 + n]; break;
        default: w = Wfrom[k * 128 + n]; break;
    }
    __nv_bfloat16 hi = __float2bfloat16(w);
    __nv_bfloat16 lo = __float2bfloat16(w - __bfloat162float(hi));
    int o = n * 136 + k;
    g_wt[tile][0][o] = hi;
    g_wt[tile][1][o] = lo;
}

// ---------------- main kernel pieces ----------------
// copy one weight tile (hi+lo contiguous, 69632B = 4352 uint4) into B tiles
__device__ __forceinline__ void copyB(char* sm, int tile, int tid) {
    const uint4* s = reinterpret_cast<const uint4*>(&g_wt[tile][0][0]);
    uint4* d = reinterpret_cast<uint4*>(sm + SO_BHI);
#pragma unroll
    for (int i = 0; i < 17; ++i) {
        int idx = tid + i * NTHR;
        d[idx] = s[idx];
    }
}

// bf16x3 GEMM: acc[3][4][4] += A[96x128] @ B^T ; warp tiles: rows (mr0+mr)*16, cols (nc0+nc)*8
__device__ __forceinline__ void gemm_main(uint32_t sb, float acc[3][4][4], int lane, int mr0, int nc0) {
#pragma unroll
    for (int mr = 0; mr < 3; ++mr)
#pragma unroll
        for (int nc = 0; nc < 4; ++nc)
#pragma unroll
            for (int e = 0; e < 4; ++e) acc[mr][nc][e] = 0.f;

    int mat = lane >> 3, r = lane & 7;
    uint32_t aoff = (uint32_t)(((mat & 1) * 8 + r) * ASTB + (mat >> 1) * 16);
    uint32_t boff = (uint32_t)(((mat >> 1) * 8 + r) * ASTB + (mat & 1) * 16);
    uint32_t aBase = sb + SO_AHI + mr0 * 16 * ASTB + aoff;
    uint32_t bBase = sb + SO_BHI + nc0 * 8 * ASTB + boff;
#pragma unroll
    for (int p = 0; p < 3; ++p) {
        uint32_t ab = aBase + (p == 1 ? (uint32_t)(SO_ALO - SO_AHI) : 0u);
        uint32_t bb = bBase + (p == 2 ? (uint32_t)(SO_BLO - SO_BHI) : 0u);
#pragma unroll
        for (int k = 0; k < 8; ++k) {
            uint32_t b0[4], b1[4];
            ldsm4(bb + k * 32, b0);
            ldsm4(bb + 16 * ASTB + k * 32, b1);
#pragma unroll
            for (int mr = 0; mr < 3; ++mr) {
                uint32_t a[4];
                ldsm4(ab + mr * 16 * ASTB + k * 32, a);
                mma16816(acc[mr][0], a, b0[0], b0[1]);
                mma16816(acc[mr][1], a, b0[2], b0[3]);
                mma16816(acc[mr][2], a, b1[0], b1[1]);
                mma16816(acc[mr][3], a, b1[2], b1[3]);
            }
        }
    }
}

// scores GEMM: A-tiles = k, B-tiles = q; warp handles 1 mrow x 3 ncols
__device__ __forceinline__ void gemm_scores(uint32_t sb, float accS[3][4], int lane, int mr, int nb) {
#pragma unroll
    for (int s = 0; s < 3; ++s)
#pragma unroll
        for (int e = 0; e < 4; ++e) accS[s][e] = 0.f;

    int mat = lane >> 3, r = lane & 7;
    uint32_t aoff = (uint32_t)(((mat & 1) * 8 + r) * ASTB + (mat >> 1) * 16);
    uint32_t boff = (uint32_t)(((mat >> 1) * 8 + r) * ASTB + (mat & 1) * 16);
    uint32_t aBase = sb + SO_AHI + mr * 16 * ASTB + aoff;
    uint32_t bBase = sb + SO_BHI + nb * 8 * ASTB + boff;
#pragma unroll
    for (int p = 0; p < 3; ++p) {
        uint32_t ab = aBase + (p == 1 ? (uint32_t)(SO_ALO - SO_AHI) : 0u);
        uint32_t bb = bBase + (p == 2 ? (uint32_t)(SO_BLO - SO_BHI) : 0u);
#pragma unroll
        for (int k = 0; k < 8; ++k) {
            uint32_t b0[4], b1[4], a[4];
            ldsm4(bb + k * 32, b0);
            ldsm4(bb + 16 * ASTB + k * 32, b1);
            ldsm4(ab + k * 32, a);
            mma16816(accS[0], a, b0[0], b0[1]);
            mma16816(accS[1], a, b0[2], b0[3]);
            mma16816(accS[2], a, b1[0], b1[1]);
        }
    }
}

// generic epilogue: dst 0 = A tiles (bf16 hi/lo), 1 = B tiles, 2 = sBuf fp32
__device__ __forceinline__ void emit(char* sm, int dst, float acc[3][4][4],
                                     const float* bias, float mul,
                                     int lane, int mr0, int nc0) {
    int g4 = lane >> 2, t2 = (lane & 3) * 2;
#pragma unroll
    for (int mr = 0; mr < 3; ++mr) {
        int r0 = (mr0 + mr) * 16 + g4;
#pragma unroll
        for (int nc = 0; nc < 4; ++nc) {
            int col = (nc0 + nc) * 8 + t2;
            float2 bb = *reinterpret_cast<const float2*>(&bias[col]);
            float v0 = (acc[mr][nc][0] + bb.x) * mul;
            float v1 = (acc[mr][nc][1] + bb.y) * mul;
            float v2 = (acc[mr][nc][2] + bb.x) * mul;
            float v3 = (acc[mr][nc][3] + bb.y) * mul;
            if (dst == 2) {
                float* bp = reinterpret_cast<float*>(sm + SO_BUF);
                *reinterpret_cast<float2*>(bp + r0 * 132 + col) = make_float2(v0, v1);
                *reinterpret_cast<float2*>(bp + (r0 + 8) * 132 + col) = make_float2(v2, v3);
            } else {
                char* hi = sm + (dst ? SO_BHI : SO_AHI);
                char* lo = sm + (dst ? SO_BLO : SO_ALO);
                split_store(hi, lo, r0, col, v0, v1);
                split_store(hi, lo, r0 + 8, col, v2, v3);
            }
        }
    }
}

__global__ void __launch_bounds__(NTHR, 1)
wan_main(const float* __restrict__ x,
         const float* __restrict__ b_tok, const float* __restrict__ g_norm,
         const float* __restrict__ b_qkv, const float* __restrict__ b_proj,
         const float* __restrict__ b_from, float* __restrict__ out) {
    extern __shared__ char sm[];
    const uint32_t sb = smem_u32(sm);
    const int tid  = threadIdx.x;
    const int lane = tid & 31;
    const int w    = tid >> 5;
    const int mr0  = (w >> 2) * 3;      // 0 or 3
    const int nc0  = (w & 3) * 4;       // 0,4,8,12
    const int g4   = lane >> 2;
    const int t2   = (lane & 3) * 2;

    const int b  = blockIdx.x >> 10;
    const int t0 = (blockIdx.x & 1023) * 4;

    float* sBias = reinterpret_cast<float*>(sm + SO_BIAS);
    float* sSq   = reinterpret_cast<float*>(sm + SO_SQ);
    float* sP    = reinterpret_cast<float*>(sm + SO_P);
    float* sBuf  = reinterpret_cast<float*>(sm + SO_BUF);
    char*  ah    = sm + SO_AHI;
    char*  al    = sm + SO_ALO;

    // ---- setup: biases, sSq, A <- x (hi/lo), B <- W_tok ----
    if (tid < 128) {
        sBias[tid]       = b_tok[tid];
        sBias[128 + tid] = g_norm[tid];
        sBias[256 + tid] = b_qkv[tid];
        sBias[384 + tid] = b_qkv[128 + tid];
        sBias[512 + tid] = b_qkv[256 + tid];
        sBias[640 + tid] = b_proj[tid];
        sBias[768 + tid] = b_from[tid];
    }
    if (tid < NROW) sSq[tid] = 0.f;
    copyB(sm, 0, tid);
#pragma unroll
    for (int it = 0; it < 12; ++it) {
        int idx = tid + it * NTHR;          // channel 0..3071 = j*128 + c
        int j = idx >> 7, c = idx & 127;
        const float4 xv = *reinterpret_cast<const float4*>(
            x + (size_t)(b * C_ + idx) * T_ + t0);
        float vals[4] = {xv.x, xv.y, xv.z, xv.w};
#pragma unroll
        for (int tl = 0; tl < 4; ++tl) {
            int row = tl * KJ + j;
            __nv_bfloat16 hi = __float2bfloat16(vals[tl]);
            __nv_bfloat16 lo = __float2bfloat16(vals[tl] - __bfloat162float(hi));
            int o = row * ASTB + c * 2;
            *reinterpret_cast<__nv_bfloat16*>(ah + o) = hi;
            *reinterpret_cast<__nv_bfloat16*>(al + o) = lo;
        }
    }
    __syncthreads();

    float acc[3][4][4];

    // ---- tok = x @ W_tok ----
    gemm_main(sb, acc, lane, mr0, nc0);
    __syncthreads();

    // tok epilogue part 1: +bias, row sums of squares; stage Wv
    {
#pragma unroll
        for (int mr = 0; mr < 3; ++mr) {
            float s0 = 0.f, s1 = 0.f;
#pragma unroll
            for (int nc = 0; nc < 4; ++nc) {
                float2 bc = *reinterpret_cast<const float2*>(&sBias[(nc0 + nc) * 8 + t2]);
                acc[mr][nc][0] += bc.x; acc[mr][nc][1] += bc.y;
                acc[mr][nc][2] += bc.x; acc[mr][nc][3] += bc.y;
                s0 += acc[mr][nc][0] * acc[mr][nc][0] + acc[mr][nc][1] * acc[mr][nc][1];
                s1 += acc[mr][nc][2] * acc[mr][nc][2] + acc[mr][nc][3] * acc[mr][nc][3];
            }
            s0 += __shfl_xor_sync(~0u, s0, 1); s0 += __shfl_xor_sync(~0u, s0, 2);
            s1 += __shfl_xor_sync(~0u, s1, 1); s1 += __shfl_xor_sync(~0u, s1, 2);
            if ((lane & 3) == 0) {
                int r0 = (mr0 + mr) * 16 + g4;
                atomicAdd(&sSq[r0], s0);
                atomicAdd(&sSq[r0 + 8], s1);
            }
        }
        copyB(sm, 3, tid);    // Wv
    }
    __syncthreads();

    // tok epilogue part 2: RMS scale * g -> A tiles
    {
        const float* gn = sBias + 128;
#pragma unroll
        for (int mr = 0; mr < 3; ++mr) {
            int r0 = (mr0 + mr) * 16 + g4;
            float sc0 = rsqrtf(sSq[r0] * (1.f / 128.f) + EPSF);
            float sc1 = rsqrtf(sSq[r0 + 8] * (1.f / 128.f) + EPSF);
#pragma unroll
            for (int nc = 0; nc < 4; ++nc) {
                int col = (nc0 + nc) * 8 + t2;
                float2 gg = *reinterpret_cast<const float2*>(&gn[col]);
                split_store(ah, al, r0, col, acc[mr][nc][0] * sc0 * gg.x,
                                              acc[mr][nc][1] * sc0 * gg.y);
                split_store(ah, al, r0 + 8, col, acc[mr][nc][2] * sc1 * gg.x,
                                                  acc[mr][nc][3] * sc1 * gg.y);
            }
        }
    }
    __syncthreads();

    // ---- v = tok @ Wv -> sBuf ----
    gemm_main(sb, acc, lane, mr0, nc0);
    __syncthreads();
    emit(sm, 2, acc, sBias + 512, 1.0f, lane, mr0, nc0);
    copyB(sm, 1, tid);    // Wq
    __syncthreads();

    // ---- q = tok @ Wq (regs) ----
    float accQ[3][4][4];
    gemm_main(sb, accQ, lane, mr0, nc0);
    __syncthreads();
    copyB(sm, 2, tid);    // Wk
    __syncthreads();

    // ---- k = tok @ Wk (regs) ----
    float accK[3][4][4];
    gemm_main(sb, accK, lane, mr0, nc0);
    __syncthreads();

    // k -> A tiles, q*SCALE -> B tiles
    emit(sm, 0, accK, sBias + 384, 1.0f, lane, mr0, nc0);
    emit(sm, 1, accQ, sBias + 256, SCALEF, lane, mr0, nc0);
    __syncthreads();

    // ---- scores: D = K @ Q^T, block-diagonal tiles only; sP[i][j] = q_i . k_j * scale ----
    {
        const int mr_tab[8] = {0, 1, 1, 2, 3, 4, 4, 5};
        const int nb_tab[8] = {0, 0, 3, 3, 6, 6, 9, 9};
        int mr = mr_tab[w], nb = nb_tab[w];
        float accS[3][4];
        gemm_scores(sb, accS, lane, mr, nb);
        int tl = nb / 3;
        int m0 = mr * 16 + g4;
        int jl0 = m0 - 24 * tl, jl1 = m0 + 8 - 24 * tl;
#pragma unroll
        for (int s = 0; s < 3; ++s) {
            int i0 = (nb + s) * 8 + t2;
            if (jl0 >= 0 && jl0 < 24) {
                sP[i0 * 24 + jl0]       = accS[s][0];
                sP[(i0 + 1) * 24 + jl0] = accS[s][1];
            }
            if (jl1 >= 0 && jl1 < 24) {
                sP[i0 * 24 + jl1]       = accS[s][2];
                sP[(i0 + 1) * 24 + jl1] = accS[s][3];
            }
        }
    }
    __syncthreads();

    // ---- softmax over 24 per row ----
    if (tid < NROW) {
        float* row = sP + tid * 24;
        float mx = row[0];
#pragma unroll
        for (int j = 1; j < KJ; ++j) mx = fmaxf(mx, row[j]);
        float sum = 0.f;
#pragma unroll
        for (int j = 0; j < KJ; ++j) { float e = __expf(row[j] - mx); row[j] = e; sum += e; }
        float inv = 1.0f / sum;
#pragma unroll
        for (int j = 0; j < KJ; ++j) row[j] *= inv;
    }
    __syncthreads();

    // ---- stage Wproj; P @ V (K=24, packed fp32) -> A tiles ----
    copyB(sm, 4, tid);
    if (tid < 192) {
        int row = tid >> 1, hh = tid & 1, cb = hh * 64;
        const float* P = sP + row * 24;
        const float* vb = sBuf + (row / 24) * 24 * 132 + cb;
        unsigned long long a2[32];
#pragma unroll
        for (int i = 0; i < 32; ++i) a2[i] = 0ull;
#pragma unroll 4
        for (int j = 0; j < KJ; ++j) {
            unsigned long long pp = pk2(P[j], P[j]);
            const float4* vr = reinterpret_cast<const float4*>(vb + j * 132);
#pragma unroll
            for (int d = 0; d < 16; ++d) {
                float4 vv = vr[d];
                fma2(a2[2 * d],     pp, pk2(vv.x, vv.y));
                fma2(a2[2 * d + 1], pp, pk2(vv.z, vv.w));
            }
        }
#pragma unroll
        for (int d = 0; d < 16; ++d) {
            float2 l  = unpk2(a2[2 * d]);
            float2 h2 = unpk2(a2[2 * d + 1]);
            split_store(ah, al, row, cb + 4 * d,     l.x, l.y);
            split_store(ah, al, row, cb + 4 * d + 2, h2.x, h2.y);
        }
    }
    __syncthreads();

    // ---- proj -> A tiles ----
    gemm_main(sb, acc, lane, mr0, nc0);
    __syncthreads();
    emit(sm, 0, acc, sBias + 640, 1.0f, lane, mr0, nc0);
    copyB(sm, 5, tid);    // Wfrom
    __syncthreads();

    // ---- from -> sBuf ----
    gemm_main(sb, acc, lane, mr0, nc0);
    __syncthreads();
    emit(sm, 2, acc, sBias + 768, 1.0f, lane, mr0, nc0);
    __syncthreads();

    // ---- residual add + coalesced float4 store ----
    {
        const size_t base = (size_t)b * C_ * T_;
#pragma unroll
        for (int it = 0; it < 12; ++it) {
            int idx = tid + it * NTHR;          // channel 0..3071
            int j = idx >> 7, c = idx & 127;
            size_t g = base + (size_t)idx * T_ + t0;
            float4 xv = *reinterpret_cast<const float4*>(x + g);
            float4 ov;
            ov.x = xv.x + sBuf[(0 * KJ + j) * 132 + c];
            ov.y = xv.y + sBuf[(1 * KJ + j) * 132 + c];
            ov.z = xv.z + sBuf[(2 * KJ + j) * 132 + c];
            ov.w = xv.w + sBuf[(3 * KJ + j) * 132 + c];
            *reinterpret_cast<float4*>(out + g) = ov;
        }
    }
}

extern "C" void kernel_launch(void* const* d_in, const int* in_sizes, int n_in,
                              void* d_out, int out_size) {
    (void)in_sizes; (void)n_in; (void)out_size;
    const float* x      = (const float*)d_in[0];
    const float* W_tok  = (const float*)d_in[1];
    const float* b_tok  = (const float*)d_in[2];
    const float* g_norm = (const float*)d_in[3];
    const float* W_qkv  = (const float*)d_in[4];
    const float* b_qkv  = (const float*)d_in[5];
    const float* W_proj = (const float*)d_in[6];
    const float* b_proj = (const float*)d_in[7];
    const float* W_from = (const float*)d_in[8];
    const float* b_from = (const float*)d_in[9];
    float* out = (float*)d_out;

    wan_prep<<<(6 * 16384) / 256, 256>>>(W_tok, W_qkv, W_proj, W_from);

    cudaFuncSetAttribute(wan_main, cudaFuncAttributeMaxDynamicSharedMemorySize, SMEM_TOTAL);
    wan_main<<<B_ * (T_ / 4), NTHR, SMEM_TOTAL>>>(
        x, b_tok, g_norm, b_qkv, b_proj, b_from, out);
}

// round 16
// speedup vs baseline: 2.4783x; 1.1019x over previous
#include <cuda_runtime.h>
#include <cuda_bf16.h>
#include <cstdint>
#include <cstddef>

// ---------------- problem constants ----------------
#define B_    4
#define C_    3072
#define T_    4096
#define KJ    24
#define NROW  96
#define NTHR  256
#define SCALEF 0.08838834764831845f
#define EPSF   1e-5f

#define ASTB  272      // bf16 tile row stride in bytes (136 elems; conflict-free for ldmatrix)

// ---------------- smem offsets (bytes) ----------------
#define SO_AHI  0
#define SO_ALO  26112          // 96*272
#define SO_BHI  52224
#define SO_BLO  87040          // +128*272
#define SO_BUF  121856         // 96*132 fp32 = 50688
#define SO_P    172544         // 96*24 fp32 = 9216
#define SO_BIAS 181760         // 896 fp32 = 3584
#define SO_SQ   185344         // 96 fp32
#define SMEM_TOTAL 185728

// preconverted weights: [tile][hi/lo][n*136 + k] bf16 (B[n][k] = W[k][n])
// tiles: 0=W_tok^T 1=Wq^T 2=Wk^T 3=Wv^T 4=W_proj^T 5=W_from^T
__device__ __align__(16) __nv_bfloat16 g_wt[6][2][128 * 136];

// ---------------- helpers ----------------
__device__ __forceinline__ uint32_t smem_u32(const void* p) {
    uint32_t a;
    asm("{ .reg .u64 t; cvta.to.shared.u64 t, %1; cvt.u32.u64 %0, t; }" : "=r"(a) : "l"(p));
    return a;
}
__device__ __forceinline__ void ldsm4(uint32_t a, uint32_t r[4]) {
    asm volatile("ldmatrix.sync.aligned.m8n8.x4.shared.b16 {%0,%1,%2,%3}, [%4];"
        : "=r"(r[0]), "=r"(r[1]), "=r"(r[2]), "=r"(r[3]) : "r"(a));
}
__device__ __forceinline__ void mma16816(float d[4], const uint32_t a[4], uint32_t b0, uint32_t b1) {
    asm volatile("mma.sync.aligned.m16n8k16.row.col.f32.bf16.bf16.f32 "
        "{%0,%1,%2,%3}, {%4,%5,%6,%7}, {%8,%9}, {%0,%1,%2,%3};"
        : "+f"(d[0]), "+f"(d[1]), "+f"(d[2]), "+f"(d[3])
        : "r"(a[0]), "r"(a[1]), "r"(a[2]), "r"(a[3]), "r"(b0), "r"(b1));
}
__device__ __forceinline__ unsigned long long pk2(float lo, float hi) {
    unsigned long long r;
    asm("mov.b64 %0, {%1, %2};" : "=l"(r) : "f"(lo), "f"(hi));
    return r;
}
__device__ __forceinline__ void fma2(unsigned long long& d, unsigned long long a, unsigned long long b) {
    asm("fma.rn.f32x2 %0, %1, %2, %0;" : "+l"(d) : "l"(a), "l"(b));
}
__device__ __forceinline__ float2 unpk2(unsigned long long v) {
    float2 r;
    asm("mov.b64 {%0, %1}, %2;" : "=f"(r.x), "=f"(r.y) : "l"(v));
    return r;
}
// cp.async (sm_80+ base ISA; compiles under compute_103)
__device__ __forceinline__ void cp16(uint32_t d, const void* g) {
    asm volatile("cp.async.cg.shared.global [%0], [%1], 16;" :: "r"(d), "l"(g));
}
__device__ __forceinline__ void cp_commit() { asm volatile("cp.async.commit_group;" ::: "memory"); }
__device__ __forceinline__ void cp_wait()   { asm volatile("cp.async.wait_all;" ::: "memory"); }

// hi/lo bf16 split + paired store into linear stride-136 tile (col even)
__device__ __forceinline__ void split_store(char* hi, char* lo, int row, int col, float a, float b) {
    __nv_bfloat162 h = __floats2bfloat162_rn(a, b);
    float ra = a - __bfloat162float(h.x);
    float rb = b - __bfloat162float(h.y);
    __nv_bfloat162 l = __floats2bfloat162_rn(ra, rb);
    int o = row * ASTB + col * 2;
    *reinterpret_cast<__nv_bfloat162*>(hi + o) = h;
    *reinterpret_cast<__nv_bfloat162*>(lo + o) = l;
}

// ---------------- prep: transpose + hi/lo split ----------------
__global__ void wan_prep(const float* __restrict__ Wtok, const float* __restrict__ Wqkv,
                         const float* __restrict__ Wproj, const float* __restrict__ Wfrom) {
    int idx = blockIdx.x * blockDim.x + threadIdx.x;     // 6*16384
    if (idx >= 6 * 16384) return;
    int tile = idx >> 14;
    int r = idx & 16383;
    int n = r >> 7, k = r & 127;
    float w;
    switch (tile) {
        case 0: w = Wtok[k * 128 + n]; break;
        case 1: w = Wqkv[k * 384 + n]; break;
        case 2: w = Wqkv[k * 384 + 128 + n]; break;
        case 3: w = Wqkv[k * 384 + 256 + n]; break;
        case 4: w = Wproj[k * 128 + n]; break;
        default: w = Wfrom[k * 128 + n]; break;
    }
    __nv_bfloat16 hi = __float2bfloat16(w);
    __nv_bfloat16 lo = __float2bfloat16(w - __bfloat162float(hi));
    int o = n * 136 + k;
    g_wt[tile][0][o] = hi;
    g_wt[tile][1][o] = lo;
}

// ---------------- async weight staging (hi+lo = 4352 uint4) ----------------
__device__ __forceinline__ void copyB_async(uint32_t sb, int tile, int tid) {
    const char* g = reinterpret_cast<const char*>(&g_wt[tile][0][0]);
    uint32_t d = sb + SO_BHI;
#pragma unroll
    for (int i = 0; i < 17; ++i) {
        int idx = (tid + i * NTHR) * 16;
        cp16(d + idx, g + idx);
    }
    cp_commit();
}

// fused bf16x3 GEMM: acc += Ah@Bh^T + Al@Bh^T + Ah@Bl^T (one k-loop, operands loaded once)
__device__ __forceinline__ void gemm_main(uint32_t sb, float acc[3][4][4], int lane, int mr0, int nc0) {
#pragma unroll
    for (int mr = 0; mr < 3; ++mr)
#pragma unroll
        for (int nc = 0; nc < 4; ++nc)
#pragma unroll
            for (int e = 0; e < 4; ++e) acc[mr][nc][e] = 0.f;

    int mat = lane >> 3, r = lane & 7;
    uint32_t aoff = (uint32_t)(((mat & 1) * 8 + r) * ASTB + (mat >> 1) * 16);
    uint32_t boff = (uint32_t)(((mat >> 1) * 8 + r) * ASTB + (mat & 1) * 16);
    uint32_t abh = sb + SO_AHI + mr0 * 16 * ASTB + aoff;
    uint32_t abl = abh + (SO_ALO - SO_AHI);
    uint32_t bbh = sb + SO_BHI + nc0 * 8 * ASTB + boff;
    uint32_t bbl = bbh + (SO_BLO - SO_BHI);
#pragma unroll
    for (int k = 0; k < 8; ++k) {
        uint32_t bh0[4], bh1[4], bl0[4], bl1[4];
        ldsm4(bbh + k * 32, bh0);
        ldsm4(bbh + 16 * ASTB + k * 32, bh1);
        ldsm4(bbl + k * 32, bl0);
        ldsm4(bbl + 16 * ASTB + k * 32, bl1);
#pragma unroll
        for (int mr = 0; mr < 3; ++mr) {
            uint32_t ah[4], al[4];
            ldsm4(abh + mr * 16 * ASTB + k * 32, ah);
            ldsm4(abl + mr * 16 * ASTB + k * 32, al);
            mma16816(acc[mr][0], ah, bh0[0], bh0[1]);
            mma16816(acc[mr][1], ah, bh0[2], bh0[3]);
            mma16816(acc[mr][2], ah, bh1[0], bh1[1]);
            mma16816(acc[mr][3], ah, bh1[2], bh1[3]);
            mma16816(acc[mr][0], al, bh0[0], bh0[1]);
            mma16816(acc[mr][1], al, bh0[2], bh0[3]);
            mma16816(acc[mr][2], al, bh1[0], bh1[1]);
            mma16816(acc[mr][3], al, bh1[2], bh1[3]);
            mma16816(acc[mr][0], ah, bl0[0], bl0[1]);
            mma16816(acc[mr][1], ah, bl0[2], bl0[3]);
            mma16816(acc[mr][2], ah, bl1[0], bl1[1]);
            mma16816(acc[mr][3], ah, bl1[2], bl1[3]);
        }
    }
}

// fused scores GEMM: A-tiles = k, B-tiles = q; warp handles 1 mrow x 3 ncols
__device__ __forceinline__ void gemm_scores(uint32_t sb, float accS[3][4], int lane, int mr, int nb) {
#pragma unroll
    for (int s = 0; s < 3; ++s)
#pragma unroll
        for (int e = 0; e < 4; ++e) accS[s][e] = 0.f;

    int mat = lane >> 3, r = lane & 7;
    uint32_t aoff = (uint32_t)(((mat & 1) * 8 + r) * ASTB + (mat >> 1) * 16);
    uint32_t boff = (uint32_t)(((mat >> 1) * 8 + r) * ASTB + (mat & 1) * 16);
    uint32_t abh = sb + SO_AHI + mr * 16 * ASTB + aoff;
    uint32_t abl = abh + (SO_ALO - SO_AHI);
    uint32_t bbh = sb + SO_BHI + nb * 8 * ASTB + boff;
    uint32_t bbl = bbh + (SO_BLO - SO_BHI);
#pragma unroll
    for (int k = 0; k < 8; ++k) {
        uint32_t bh0[4], bh1[4], bl0[4], bl1[4], ah[4], al[4];
        ldsm4(bbh + k * 32, bh0);
        ldsm4(bbh + 16 * ASTB + k * 32, bh1);
        ldsm4(bbl + k * 32, bl0);
        ldsm4(bbl + 16 * ASTB + k * 32, bl1);
        ldsm4(abh + k * 32, ah);
        ldsm4(abl + k * 32, al);
        mma16816(accS[0], ah, bh0[0], bh0[1]);
        mma16816(accS[1], ah, bh0[2], bh0[3]);
        mma16816(accS[2], ah, bh1[0], bh1[1]);
        mma16816(accS[0], al, bh0[0], bh0[1]);
        mma16816(accS[1], al, bh0[2], bh0[3]);
        mma16816(accS[2], al, bh1[0], bh1[1]);
        mma16816(accS[0], ah, bl0[0], bl0[1]);
        mma16816(accS[1], ah, bl0[2], bl0[3]);
        mma16816(accS[2], ah, bl1[0], bl1[1]);
    }
}

// generic epilogue: dst 0 = A tiles (bf16 hi/lo), 1 = B tiles, 2 = sBuf fp32
__device__ __forceinline__ void emit(char* sm, int dst, float acc[3][4][4],
                                     const float* bias, float mul,
                                     int lane, int mr0, int nc0) {
    int g4 = lane >> 2, t2 = (lane & 3) * 2;
#pragma unroll
    for (int mr = 0; mr < 3; ++mr) {
        int r0 = (mr0 + mr) * 16 + g4;
#pragma unroll
        for (int nc = 0; nc < 4; ++nc) {
            int col = (nc0 + nc) * 8 + t2;
            float2 bb = *reinterpret_cast<const float2*>(&bias[col]);
            float v0 = (acc[mr][nc][0] + bb.x) * mul;
            float v1 = (acc[mr][nc][1] + bb.y) * mul;
            float v2 = (acc[mr][nc][2] + bb.x) * mul;
            float v3 = (acc[mr][nc][3] + bb.y) * mul;
            if (dst == 2) {
                float* bp = reinterpret_cast<float*>(sm + SO_BUF);
                *reinterpret_cast<float2*>(bp + r0 * 132 + col) = make_float2(v0, v1);
                *reinterpret_cast<float2*>(bp + (r0 + 8) * 132 + col) = make_float2(v2, v3);
            } else {
                char* hi = sm + (dst ? SO_BHI : SO_AHI);
                char* lo = sm + (dst ? SO_BLO : SO_ALO);
                split_store(hi, lo, r0, col, v0, v1);
                split_store(hi, lo, r0 + 8, col, v2, v3);
            }
        }
    }
}

__global__ void __launch_bounds__(NTHR, 1)
wan_main(const float* __restrict__ x,
         const float* __restrict__ b_tok, const float* __restrict__ g_norm,
         const float* __restrict__ b_qkv, const float* __restrict__ b_proj,
         const float* __restrict__ b_from, float* __restrict__ out) {
    extern __shared__ char sm[];
    const uint32_t sb = smem_u32(sm);
    const int tid  = threadIdx.x;
    const int lane = tid & 31;
    const int w    = tid >> 5;
    const int mr0  = (w >> 2) * 3;      // 0 or 3
    const int nc0  = (w & 3) * 4;       // 0,4,8,12
    const int g4   = lane >> 2;
    const int t2   = (lane & 3) * 2;

    const int b  = blockIdx.x >> 10;
    const int t0 = (blockIdx.x & 1023) * 4;

    float* sBias = reinterpret_cast<float*>(sm + SO_BIAS);
    float* sSq   = reinterpret_cast<float*>(sm + SO_SQ);
    float* sP    = reinterpret_cast<float*>(sm + SO_P);
    float* sBuf  = reinterpret_cast<float*>(sm + SO_BUF);
    char*  ah    = sm + SO_AHI;
    char*  al    = sm + SO_ALO;

    // ---- setup: async-stage W_tok, then biases + A <- x (hi/lo) while it flies ----
    copyB_async(sb, 0, tid);
    if (tid < 128) {
        sBias[tid]       = b_tok[tid];
        sBias[128 + tid] = g_norm[tid];
        sBias[256 + tid] = b_qkv[tid];
        sBias[384 + tid] = b_qkv[128 + tid];
        sBias[512 + tid] = b_qkv[256 + tid];
        sBias[640 + tid] = b_proj[tid];
        sBias[768 + tid] = b_from[tid];
    }
    if (tid < NROW) sSq[tid] = 0.f;
#pragma unroll
    for (int it = 0; it < 12; ++it) {
        int idx = tid + it * NTHR;          // channel 0..3071 = j*128 + c
        int j = idx >> 7, c = idx & 127;
        const float4 xv = *reinterpret_cast<const float4*>(
            x + (size_t)(b * C_ + idx) * T_ + t0);
        float vals[4] = {xv.x, xv.y, xv.z, xv.w};
#pragma unroll
        for (int tl = 0; tl < 4; ++tl) {
            int row = tl * KJ + j;
            __nv_bfloat16 hi = __float2bfloat16(vals[tl]);
            __nv_bfloat16 lo = __float2bfloat16(vals[tl] - __bfloat162float(hi));
            int o = row * ASTB + c * 2;
            *reinterpret_cast<__nv_bfloat16*>(ah + o) = hi;
            *reinterpret_cast<__nv_bfloat16*>(al + o) = lo;
        }
    }
    cp_wait();
    __syncthreads();

    float acc[3][4][4];

    // ---- tok = x @ W_tok ----
    gemm_main(sb, acc, lane, mr0, nc0);
    __syncthreads();

    // tok epilogue part 1: +bias, row sums of squares; async-stage Wv
    copyB_async(sb, 3, tid);
    {
#pragma unroll
        for (int mr = 0; mr < 3; ++mr) {
            float s0 = 0.f, s1 = 0.f;
#pragma unroll
            for (int nc = 0; nc < 4; ++nc) {
                float2 bc = *reinterpret_cast<const float2*>(&sBias[(nc0 + nc) * 8 + t2]);
                acc[mr][nc][0] += bc.x; acc[mr][nc][1] += bc.y;
                acc[mr][nc][2] += bc.x; acc[mr][nc][3] += bc.y;
                s0 += acc[mr][nc][0] * acc[mr][nc][0] + acc[mr][nc][1] * acc[mr][nc][1];
                s1 += acc[mr][nc][2] * acc[mr][nc][2] + acc[mr][nc][3] * acc[mr][nc][3];
            }
            s0 += __shfl_xor_sync(~0u, s0, 1); s0 += __shfl_xor_sync(~0u, s0, 2);
            s1 += __shfl_xor_sync(~0u, s1, 1); s1 += __shfl_xor_sync(~0u, s1, 2);
            if ((lane & 3) == 0) {
                int r0 = (mr0 + mr) * 16 + g4;
                atomicAdd(&sSq[r0], s0);
                atomicAdd(&sSq[r0 + 8], s1);
            }
        }
    }
    __syncthreads();

    // tok epilogue part 2: RMS scale * g -> A tiles
    {
        const float* gn = sBias + 128;
#pragma unroll
        for (int mr = 0; mr < 3; ++mr) {
            int r0 = (mr0 + mr) * 16 + g4;
            float sc0 = rsqrtf(sSq[r0] * (1.f / 128.f) + EPSF);
            float sc1 = rsqrtf(sSq[r0 + 8] * (1.f / 128.f) + EPSF);
#pragma unroll
            for (int nc = 0; nc < 4; ++nc) {
                int col = (nc0 + nc) * 8 + t2;
                float2 gg = *reinterpret_cast<const float2*>(&gn[col]);
                split_store(ah, al, r0, col, acc[mr][nc][0] * sc0 * gg.x,
                                              acc[mr][nc][1] * sc0 * gg.y);
                split_store(ah, al, r0 + 8, col, acc[mr][nc][2] * sc1 * gg.x,
                                                  acc[mr][nc][3] * sc1 * gg.y);
            }
        }
    }
    cp_wait();
    __syncthreads();

    // ---- v = tok @ Wv -> sBuf ----
    gemm_main(sb, acc, lane, mr0, nc0);
    __syncthreads();
    copyB_async(sb, 1, tid);    // Wq
    emit(sm, 2, acc, sBias + 512, 1.0f, lane, mr0, nc0);
    cp_wait();
    __syncthreads();

    // ---- q = tok @ Wq (regs) ----
    float accQ[3][4][4];
    gemm_main(sb, accQ, lane, mr0, nc0);
    __syncthreads();
    copyB_async(sb, 2, tid);    // Wk
    cp_wait();
    __syncthreads();

    // ---- k = tok @ Wk (regs) ----
    float accK[3][4][4];
    gemm_main(sb, accK, lane, mr0, nc0);
    __syncthreads();

    // k -> A tiles, q*SCALE -> B tiles
    emit(sm, 0, accK, sBias + 384, 1.0f, lane, mr0, nc0);
    emit(sm, 1, accQ, sBias + 256, SCALEF, lane, mr0, nc0);
    __syncthreads();

    // ---- scores: D = K @ Q^T, block-diagonal tiles only ----
    {
        const int mr_tab[8] = {0, 1, 1, 2, 3, 4, 4, 5};
        const int nb_tab[8] = {0, 0, 3, 3, 6, 6, 9, 9};
        int mr = mr_tab[w], nb = nb_tab[w];
        float accS[3][4];
        gemm_scores(sb, accS, lane, mr, nb);
        int tl = nb / 3;
        int m0 = mr * 16 + g4;
        int jl0 = m0 - 24 * tl, jl1 = m0 + 8 - 24 * tl;
#pragma unroll
        for (int s = 0; s < 3; ++s) {
            int i0 = (nb + s) * 8 + t2;
            if (jl0 >= 0 && jl0 < 24) {
                sP[i0 * 24 + jl0]       = accS[s][0];
                sP[(i0 + 1) * 24 + jl0] = accS[s][1];
            }
            if (jl1 >= 0 && jl1 < 24) {
                sP[i0 * 24 + jl1]       = accS[s][2];
                sP[(i0 + 1) * 24 + jl1] = accS[s][3];
            }
        }
    }
    __syncthreads();

    // ---- softmax over 24 per row ----
    if (tid < NROW) {
        float* row = sP + tid * 24;
        float mx = row[0];
#pragma unroll
        for (int j = 1; j < KJ; ++j) mx = fmaxf(mx, row[j]);
        float sum = 0.f;
#pragma unroll
        for (int j = 0; j < KJ; ++j) { float e = __expf(row[j] - mx); row[j] = e; sum += e; }
        float inv = 1.0f / sum;
#pragma unroll
        for (int j = 0; j < KJ; ++j) row[j] *= inv;
    }
    __syncthreads();

    // ---- async-stage Wproj; P @ V (K=24, packed fp32) -> A tiles ----
    copyB_async(sb, 4, tid);
    if (tid < 192) {
        int row = tid >> 1, hh = tid & 1, cb = hh * 64;
        const float* P = sP + row * 24;
        const float* vb = sBuf + (row / 24) * 24 * 132 + cb;
        unsigned long long a2[32];
#pragma unroll
        for (int i = 0; i < 32; ++i) a2[i] = 0ull;
#pragma unroll 4
        for (int j = 0; j < KJ; ++j) {
            unsigned long long pp = pk2(P[j], P[j]);
            const float4* vr = reinterpret_cast<const float4*>(vb + j * 132);
#pragma unroll
            for (int d = 0; d < 16; ++d) {
                float4 vv = vr[d];
                fma2(a2[2 * d],     pp, pk2(vv.x, vv.y));
                fma2(a2[2 * d + 1], pp, pk2(vv.z, vv.w));
            }
        }
#pragma unroll
        for (int d = 0; d < 16; ++d) {
            float2 l  = unpk2(a2[2 * d]);
            float2 h2 = unpk2(a2[2 * d + 1]);
            split_store(ah, al, row, cb + 4 * d,     l.x, l.y);
            split_store(ah, al, row, cb + 4 * d + 2, h2.x, h2.y);
        }
    }
    cp_wait();
    __syncthreads();

    // ---- proj -> A tiles ----
    gemm_main(sb, acc, lane, mr0, nc0);
    __syncthreads();
    copyB_async(sb, 5, tid);    // Wfrom
    emit(sm, 0, acc, sBias + 640, 1.0f, lane, mr0, nc0);
    cp_wait();
    __syncthreads();

    // ---- from -> sBuf ----
    gemm_main(sb, acc, lane, mr0, nc0);
    __syncthreads();
    emit(sm, 2, acc, sBias + 768, 1.0f, lane, mr0, nc0);
    __syncthreads();

    // ---- residual add + coalesced float4 store ----
    {
        const size_t base = (size_t)b * C_ * T_;
#pragma unroll
        for (int it = 0; it < 12; ++it) {
            int idx = tid + it * NTHR;          // channel 0..3071
            int j = idx >> 7, c = idx & 127;
            size_t g = base + (size_t)idx * T_ + t0;
            float4 xv = *reinterpret_cast<const float4*>(x + g);
            float4 ov;
            ov.x = xv.x + sBuf[(0 * KJ + j) * 132 + c];
            ov.y = xv.y + sBuf[(1 * KJ + j) * 132 + c];
            ov.z = xv.z + sBuf[(2 * KJ + j) * 132 + c];
            ov.w = xv.w + sBuf[(3 * KJ + j) * 132 + c];
            *reinterpret_cast<float4*>(out + g) = ov;
        }
    }
}

extern "C" void kernel_launch(void* const* d_in, const int* in_sizes, int n_in,
                              void* d_out, int out_size) {
    (void)in_sizes; (void)n_in; (void)out_size;
    const float* x      = (const float*)d_in[0];
    const float* W_tok  = (const float*)d_in[1];
    const float* b_tok  = (const float*)d_in[2];
    const float* g_norm = (const float*)d_in[3];
    const float* W_qkv  = (const float*)d_in[4];
    const float* b_qkv  = (const float*)d_in[5];
    const float* W_proj = (const float*)d_in[6];
    const float* b_proj = (const float*)d_in[7];
    const float* W_from = (const float*)d_in[8];
    const float* b_from = (const float*)d_in[9];
    float* out = (float*)d_out;

    wan_prep<<<(6 * 16384) / 256, 256>>>(W_tok, W_qkv, W_proj, W_from);

    cudaFuncSetAttribute(wan_main, cudaFuncAttributeMaxDynamicSharedMemorySize, SMEM_TOTAL);
    wan_main<<<B_ * (T_ / 4), NTHR, SMEM_TOTAL>>>(
        x, b_tok, g_norm, b_qkv, b_proj, b_from, out);
}